// round 6
// baseline (speedup 1.0000x reference)
#include <cuda_runtime.h>

// BTT forward: two chained batched GEMMs, fp32, f32x2 packed-FMA microkernel.
//
//   Stage 1 (per j):  Z[b, j, n] = sum_x  x[b, j*64+x] * core0[j*16384 + x*256 + n]
//                     (n = y*4+r, N=256, K=64, M=8192)
//   Stage 2 (per i'): out[b, y*64+i'] = sum_k Z[b, (k>>2)*256 + i'*4 + (k&3)]
//                                             * core1[(k>>2)*16384 + y*256 + i'*4 + (k&3)]
//                                       + bias[y*64+i']
//                     (k = x'*4+a, K=256, N=64, M=8192)
//
// Batch processed in 8 slices of 1024 rows; the 64 MiB fp32 intermediate for a
// slice stays L2-resident between the stage-1 write and the stage-2 read.

#define SLICE 1024
#define NSLICE 8

// Scratch: Z[b_local][j][n], 1024 * 64 * 256 floats = 64 MiB
__device__ float g_Z[(size_t)SLICE * 64 * 256];

__device__ __forceinline__ void fma2(unsigned long long& d,
                                     unsigned long long a,
                                     unsigned long long b) {
    asm("fma.rn.f32x2 %0, %1, %2, %0;" : "+l"(d) : "l"(a), "l"(b));
}
__device__ __forceinline__ unsigned long long dup2(float v) {
    unsigned long long r;
    asm("mov.b64 %0, {%1, %1};" : "=l"(r) : "f"(v));
    return r;
}
__device__ __forceinline__ float2 unpack2(unsigned long long u) {
    float2 f;
    asm("mov.b64 {%0, %1}, %2;" : "=f"(f.x), "=f"(f.y) : "l"(u));
    return f;
}

// ---------------------------------------------------------------------------
// Stage 1: per-j GEMM (M=SLICE, N=256, K=64). BM=128, BN=128, BK=32.
// 256 threads, 8x8 per-thread tile (n paired into 4 f32x2 accumulator pairs).
// grid = (2 n-tiles, SLICE/128 m-tiles, 64 j)
// ---------------------------------------------------------------------------
__global__ void __launch_bounds__(256) s1_kernel(const float* __restrict__ x,
                                                 const float* __restrict__ c0,
                                                 int rowbase) {
    __shared__ float As[32][132];  // [k][m]
    __shared__ float Bs[32][132];  // [k][n]

    const int tid  = threadIdx.x;
    const int j    = blockIdx.z;
    const int row0 = blockIdx.y * 128;
    const int col0 = blockIdx.x * 128;
    const int tm0  = (tid >> 4) * 8;   // 16 m-groups * 8
    const int tn0  = (tid & 15) * 8;   // 16 n-groups * 8

    unsigned long long acc[8][4];
#pragma unroll
    for (int m = 0; m < 8; m++)
#pragma unroll
        for (int np = 0; np < 4; np++) acc[m][np] = 0ull;

    for (int kt = 0; kt < 2; kt++) {
        // --- load A tile (128 m x 32 k), transposed into As[k][m] ---
        {
            const int kq = tid & 7;   // float4 index along k
            const int r0 = tid >> 3;  // 0..31
#pragma unroll
            for (int it = 0; it < 4; it++) {
                int m = r0 + it * 32;
                float4 v = *reinterpret_cast<const float4*>(
                    x + (size_t)(rowbase + row0 + m) * 4096 + j * 64 + kt * 32 + kq * 4);
                As[kq * 4 + 0][m] = v.x;
                As[kq * 4 + 1][m] = v.y;
                As[kq * 4 + 2][m] = v.z;
                As[kq * 4 + 3][m] = v.w;
            }
        }
        // --- load B tile (32 k x 128 n), contiguous rows ---
        {
            const int nq = tid & 31;
            const int kb = tid >> 5;  // 0..7
#pragma unroll
            for (int it = 0; it < 4; it++) {
                int kk = kb + it * 8;
                float4 v = *reinterpret_cast<const float4*>(
                    c0 + (size_t)j * 16384 + (size_t)(kt * 32 + kk) * 256 + col0 + nq * 4);
                *reinterpret_cast<float4*>(&Bs[kk][nq * 4]) = v;
            }
        }
        __syncthreads();

#pragma unroll 4
        for (int kk = 0; kk < 32; kk++) {
            float4 a0 = *reinterpret_cast<const float4*>(&As[kk][tm0]);
            float4 a1 = *reinterpret_cast<const float4*>(&As[kk][tm0 + 4]);
            unsigned long long bp[4];
#pragma unroll
            for (int np = 0; np < 4; np++)
                bp[np] = *reinterpret_cast<const unsigned long long*>(&Bs[kk][tn0 + 2 * np]);
            float av[8] = {a0.x, a0.y, a0.z, a0.w, a1.x, a1.y, a1.z, a1.w};
#pragma unroll
            for (int m = 0; m < 8; m++) {
                unsigned long long ad = dup2(av[m]);
#pragma unroll
                for (int np = 0; np < 4; np++) fma2(acc[m][np], ad, bp[np]);
            }
        }
        __syncthreads();
    }

    // --- epilogue: Z[b_local][j][n], contiguous in n ---
#pragma unroll
    for (int m = 0; m < 8; m++) {
        float* zp = g_Z + (size_t)(row0 + tm0 + m) * 16384 + j * 256 + col0 + tn0;
        float2 p0 = unpack2(acc[m][0]);
        float2 p1 = unpack2(acc[m][1]);
        float2 p2 = unpack2(acc[m][2]);
        float2 p3 = unpack2(acc[m][3]);
        *reinterpret_cast<float4*>(zp)     = make_float4(p0.x, p0.y, p1.x, p1.y);
        *reinterpret_cast<float4*>(zp + 4) = make_float4(p2.x, p2.y, p3.x, p3.y);
    }
}

// ---------------------------------------------------------------------------
// Stage 2: per-i' GEMM (M=SLICE, N=64, K=256). BM=256, BN=64, BK=32.
// 256 threads, 8x8 per-thread tile.
// grid = (64 i'  [fastest -> L2 line sharing], SLICE/256 m-tiles)
// ---------------------------------------------------------------------------
__global__ void __launch_bounds__(256) s2_kernel(const float* __restrict__ c1,
                                                 const float* __restrict__ bias,
                                                 float* __restrict__ out,
                                                 int rowbase) {
    __shared__ float As[32][260];  // [k][m]
    __shared__ float Bs[32][68];   // [k][n=y']

    const int tid  = threadIdx.x;
    const int ii   = blockIdx.x;        // i' in 0..63
    const int row0 = blockIdx.y * 256;
    const int tm0  = (tid >> 3) * 8;    // 32 m-groups * 8
    const int tn0  = (tid & 7) * 8;     // 8 n-groups * 8

    unsigned long long acc[8][4];
#pragma unroll
    for (int m = 0; m < 8; m++)
#pragma unroll
        for (int np = 0; np < 4; np++) acc[m][np] = 0ull;

    for (int kt = 0; kt < 8; kt++) {
        // --- load A tile (256 m x 32 k); k = xi*4 + a, x' = kt*8 + xi ---
        {
            const int xi = tid & 7;
            const int r0 = tid >> 3;  // 0..31
#pragma unroll
            for (int it = 0; it < 8; it++) {
                int b = r0 + it * 32;
                float4 v = *reinterpret_cast<const float4*>(
                    g_Z + (size_t)(row0 + b) * 16384 + (size_t)(kt * 8 + xi) * 256 + ii * 4);
                As[xi * 4 + 0][b] = v.x;
                As[xi * 4 + 1][b] = v.y;
                As[xi * 4 + 2][b] = v.z;
                As[xi * 4 + 3][b] = v.w;
            }
        }
        // --- load B tile (32 k x 64 y'); core1[x'*16384 + y*256 + ii*4 + a] ---
        {
            const int y  = tid & 63;
            const int xb = tid >> 6;  // 0..3
#pragma unroll
            for (int it = 0; it < 2; it++) {
                int xi = xb + it * 4;
                float4 v = *reinterpret_cast<const float4*>(
                    c1 + (size_t)(kt * 8 + xi) * 16384 + (size_t)y * 256 + ii * 4);
                Bs[xi * 4 + 0][y] = v.x;
                Bs[xi * 4 + 1][y] = v.y;
                Bs[xi * 4 + 2][y] = v.z;
                Bs[xi * 4 + 3][y] = v.w;
            }
        }
        __syncthreads();

#pragma unroll 4
        for (int kk = 0; kk < 32; kk++) {
            float4 a0 = *reinterpret_cast<const float4*>(&As[kk][tm0]);
            float4 a1 = *reinterpret_cast<const float4*>(&As[kk][tm0 + 4]);
            unsigned long long bp[4];
#pragma unroll
            for (int np = 0; np < 4; np++)
                bp[np] = *reinterpret_cast<const unsigned long long*>(&Bs[kk][tn0 + 2 * np]);
            float av[8] = {a0.x, a0.y, a0.z, a0.w, a1.x, a1.y, a1.z, a1.w};
#pragma unroll
            for (int m = 0; m < 8; m++) {
                unsigned long long ad = dup2(av[m]);
#pragma unroll
                for (int np = 0; np < 4; np++) fma2(acc[m][np], ad, bp[np]);
            }
        }
        __syncthreads();
    }

    // --- epilogue: out[b, y*64 + i'] = acc + bias[y*64 + i'] ---
    float bv[8];
#pragma unroll
    for (int n = 0; n < 8; n++) bv[n] = bias[(tn0 + n) * 64 + ii];

#pragma unroll
    for (int m = 0; m < 8; m++) {
        float2 p0 = unpack2(acc[m][0]);
        float2 p1 = unpack2(acc[m][1]);
        float2 p2 = unpack2(acc[m][2]);
        float2 p3 = unpack2(acc[m][3]);
        float vals[8] = {p0.x, p0.y, p1.x, p1.y, p2.x, p2.y, p3.x, p3.y};
        float* op = out + (size_t)(rowbase + row0 + tm0 + m) * 4096;
#pragma unroll
        for (int n = 0; n < 8; n++) {
            op[(tn0 + n) * 64 + ii] = vals[n] + bv[n];
        }
    }
}

extern "C" void kernel_launch(void* const* d_in, const int* in_sizes, int n_in,
                              void* d_out, int out_size) {
    const float* x    = (const float*)d_in[0];  // (8192, 4096)
    const float* c0   = (const float*)d_in[1];  // (64,64,64,4,1)
    const float* c1   = (const float*)d_in[2];  // (64,64,64,1,4)
    const float* bias = (const float*)d_in[3];  // (4096,)
    float* out = (float*)d_out;                 // (8192, 4096)

    for (int s = 0; s < NSLICE; s++) {
        dim3 g1(2, SLICE / 128, 64);
        s1_kernel<<<g1, 256>>>(x, c0, s * SLICE);
        dim3 g2(64, SLICE / 256);
        s2_kernel<<<g2, 256>>>(c1, bias, out, s * SLICE);
    }
}

// round 8
// speedup vs baseline: 1.3534x; 1.3534x over previous
#include <cuda_runtime.h>
#include <cstdint>

// BTT forward, fp32, f32x2 FFMA2 microkernels, transposed intermediate.
//
// Stage 1 (per j):  Z[b, n] = sum_x x[b, j*64+x] * core0[j*16384 + x*256 + n]
//   n = y*4+r.  Stored TRANSPOSED:  Zt[row][b],  row = (y*64 + j)*4 + r
//                                              = i'*256 + x'*4 + a   (stage-2 view)
// Stage 2 (per i'): out[b, y*64+i'] = sum_{k=0..255} Zt[i'*256 + k][b]
//                                     * core1[(k>>2)*16384 + y*256 + i'*4 + (k&3)]
//                                     + bias[y*64+i']
//   A-panel for i' = Zt rows [i'*256, i'*256+256): contiguous, cp.async-friendly.

__device__ float g_Z[(size_t)16384 * 8192];  // 512 MiB, Zt[row][b]

__device__ __forceinline__ void fma2(unsigned long long& d,
                                     unsigned long long a,
                                     unsigned long long b) {
    asm("fma.rn.f32x2 %0, %1, %2, %0;" : "+l"(d) : "l"(a), "l"(b));
}
__device__ __forceinline__ unsigned long long dup2(float v) {
    unsigned long long r;
    asm("mov.b64 %0, {%1, %1};" : "=l"(r) : "f"(v));
    return r;
}
__device__ __forceinline__ float2 unpack2(unsigned long long u) {
    float2 f;
    asm("mov.b64 {%0, %1}, %2;" : "=f"(f.x), "=f"(f.y) : "l"(u));
    return f;
}
__device__ __forceinline__ void cp16(uint32_t dst, const void* src) {
    asm volatile("cp.async.cg.shared.global [%0], [%1], 16;" :: "r"(dst), "l"(src));
}
#define CP_COMMIT() asm volatile("cp.async.commit_group;")
#define CP_WAIT0()  asm volatile("cp.async.wait_group 0;")

// ---------------------------------------------------------------------------
// Stage 1: per-j GEMM (M=8192 b, N=256 n, K=64 x). BM=128, BN=128, BK=64.
// 256 threads, 8x8 per-thread tile. grid = (2, 64 mtiles, 64 j).
// smem: As[128][68] (m-major, k inner), Bs[64][132] (k-major, n inner).
// ---------------------------------------------------------------------------
#define S1_SMEM ((128 * 68 + 64 * 132) * 4)

__global__ void __launch_bounds__(256, 2) s1_kernel(const float* __restrict__ x,
                                                    const float* __restrict__ c0) {
    extern __shared__ float sm1[];
    float (*As)[68]  = reinterpret_cast<float(*)[68]>(sm1);
    float (*Bs)[132] = reinterpret_cast<float(*)[132]>(sm1 + 128 * 68);

    const int tid  = threadIdx.x;
    const int col0 = blockIdx.x * 128;
    const int row0 = blockIdx.y * 128;
    const int j    = blockIdx.z;

    // --- load A tile (128 b x 64 k), natural layout As[m][k] ---
    {
        const int kq = tid & 15;   // float4 along k
        const int m0 = tid >> 4;   // 0..15
        const float* src = x + (size_t)(row0 + m0) * 4096 + j * 64 + kq * 4;
#pragma unroll
        for (int it = 0; it < 8; it++) {
            float4 v = *reinterpret_cast<const float4*>(src + (size_t)it * 16 * 4096);
            *reinterpret_cast<float4*>(&As[m0 + it * 16][kq * 4]) = v;
        }
    }
    // --- load B tile (64 k x 128 n), contiguous rows ---
    {
        const int nq = tid & 31;
        const int k0 = tid >> 5;   // 0..7
        const float* src = c0 + (size_t)j * 16384 + (size_t)k0 * 256 + col0 + nq * 4;
#pragma unroll
        for (int it = 0; it < 8; it++) {
            float4 v = *reinterpret_cast<const float4*>(src + it * 8 * 256);
            *reinterpret_cast<float4*>(&Bs[k0 + it * 8][nq * 4]) = v;
        }
    }
    __syncthreads();

    const int tm0 = (tid >> 4) * 8;
    const int tn0 = (tid & 15) * 8;

    unsigned long long acc[8][4];
#pragma unroll
    for (int m = 0; m < 8; m++)
#pragma unroll
        for (int np = 0; np < 4; np++) acc[m][np] = 0ull;

#pragma unroll 2
    for (int k4 = 0; k4 < 16; k4++) {
        float4 af[8];
#pragma unroll
        for (int m = 0; m < 8; m++)
            af[m] = *reinterpret_cast<const float4*>(&As[tm0 + m][k4 * 4]);
#pragma unroll
        for (int kk = 0; kk < 4; kk++) {
            const int k = k4 * 4 + kk;
            ulonglong2 q0 = *reinterpret_cast<const ulonglong2*>(&Bs[k][tn0]);
            ulonglong2 q1 = *reinterpret_cast<const ulonglong2*>(&Bs[k][tn0 + 4]);
#pragma unroll
            for (int m = 0; m < 8; m++) {
                float a = (kk == 0) ? af[m].x : (kk == 1) ? af[m].y
                        : (kk == 2) ? af[m].z : af[m].w;
                unsigned long long ad = dup2(a);
                fma2(acc[m][0], ad, q0.x);
                fma2(acc[m][1], ad, q0.y);
                fma2(acc[m][2], ad, q1.x);
                fma2(acc[m][3], ad, q1.y);
            }
        }
    }

    // --- epilogue: transposed store, Zt[(n>>2)*256 + j*4 + (n&3)][b] ---
#pragma unroll
    for (int np = 0; np < 4; np++) {
        float2 p[8];
#pragma unroll
        for (int m = 0; m < 8; m++) p[m] = unpack2(acc[m][np]);
#pragma unroll
        for (int half = 0; half < 2; half++) {
            const int n = col0 + tn0 + np * 2 + half;
            const size_t row = (size_t)((n >> 2) * 64 + j) * 4 + (n & 3);
            float* zp = g_Z + row * 8192 + row0 + tm0;
            float4 v0, v1;
            if (half == 0) {
                v0 = make_float4(p[0].x, p[1].x, p[2].x, p[3].x);
                v1 = make_float4(p[4].x, p[5].x, p[6].x, p[7].x);
            } else {
                v0 = make_float4(p[0].y, p[1].y, p[2].y, p[3].y);
                v1 = make_float4(p[4].y, p[5].y, p[6].y, p[7].y);
            }
            *reinterpret_cast<float4*>(zp)     = v0;
            *reinterpret_cast<float4*>(zp + 4) = v1;
        }
    }
}

// ---------------------------------------------------------------------------
// Stage 2: per-i' GEMM (M=8192 b, N=64 y, K=256). BM=256, BN=64, BK=32.
// 256 threads, 8x8 tile. cp.async double-buffered A; register-staged B.
// grid = (64 i', 32 mtiles).
// smem: As[2][32][256] (k-major, b inner), Bs[2][32][68] (k-major, y inner).
// ---------------------------------------------------------------------------
#define S2_SMEM ((2 * 32 * 256 + 2 * 32 * 68) * 4)

__global__ void __launch_bounds__(256, 2) s2_kernel(const float* __restrict__ c1,
                                                    const float* __restrict__ bias,
                                                    float* __restrict__ out) {
    extern __shared__ float sm2[];
    float* As = sm2;                 // [2][32][256]
    float* Bs = sm2 + 2 * 32 * 256;  // [2][32][68]

    const int tid  = threadIdx.x;
    const int ii   = blockIdx.x;         // i'
    const int row0 = blockIdx.y * 256;
    const int tm0  = (tid >> 3) * 8;
    const int tn0  = (tid & 7) * 8;

    // A loader mapping: one k-row per thread-octet, 8 x 16B chunks
    const int ak = tid >> 3;             // 0..31
    const int ac = (tid & 7) * 4;        // float4 lane offset within 32-float chunk
    const uint32_t as_dst0 = (uint32_t)__cvta_generic_to_shared(As + ak * 256 + ac);
    const float* a_src0 = g_Z + (size_t)(ii * 256 + ak) * 8192 + row0 + ac;

    // B loader mapping
    const int by = tid & 63;
    const int bx = tid >> 6;             // 0..3

    float4 breg[2];

    auto loadA = [&](int kt, int buf) {
        const float* src = a_src0 + (size_t)(kt * 32) * 8192;
        uint32_t dst = as_dst0 + buf * 8192 * 4;
#pragma unroll
        for (int q = 0; q < 8; q++)
            cp16(dst + q * 32 * 4, src + q * 32);
        CP_COMMIT();
    };
    auto ldgB = [&](int kt) {
#pragma unroll
        for (int it = 0; it < 2; it++)
            breg[it] = *reinterpret_cast<const float4*>(
                c1 + (size_t)(kt * 8 + bx + it * 4) * 16384 + (size_t)by * 256 + ii * 4);
    };
    auto stsB = [&](int buf) {
#pragma unroll
        for (int it = 0; it < 2; it++) {
            float* bp = Bs + buf * 2176 + (bx + it * 4) * 4 * 68 + by;
            bp[0]       = breg[it].x;
            bp[68]      = breg[it].y;
            bp[136]     = breg[it].z;
            bp[204]     = breg[it].w;
        }
    };

    unsigned long long acc[8][4];
#pragma unroll
    for (int m = 0; m < 8; m++)
#pragma unroll
        for (int np = 0; np < 4; np++) acc[m][np] = 0ull;

    // prologue
    ldgB(0);
    loadA(0, 0);
    stsB(0);
    CP_WAIT0();
    __syncthreads();

#pragma unroll 1
    for (int kt = 0; kt < 8; kt++) {
        const int cur = kt & 1;
        if (kt < 7) {
            ldgB(kt + 1);
            loadA(kt + 1, cur ^ 1);
        }
        const float* Ab = As + cur * 8192;
        const float* Bb = Bs + cur * 2176;
#pragma unroll 8
        for (int kk = 0; kk < 32; kk++) {
            float4 a0 = *reinterpret_cast<const float4*>(Ab + kk * 256 + tm0);
            float4 a1 = *reinterpret_cast<const float4*>(Ab + kk * 256 + tm0 + 4);
            ulonglong2 q0 = *reinterpret_cast<const ulonglong2*>(Bb + kk * 68 + tn0);
            ulonglong2 q1 = *reinterpret_cast<const ulonglong2*>(Bb + kk * 68 + tn0 + 4);
            float av[8] = {a0.x, a0.y, a0.z, a0.w, a1.x, a1.y, a1.z, a1.w};
#pragma unroll
            for (int m = 0; m < 8; m++) {
                unsigned long long ad = dup2(av[m]);
                fma2(acc[m][0], ad, q0.x);
                fma2(acc[m][1], ad, q0.y);
                fma2(acc[m][2], ad, q1.x);
                fma2(acc[m][3], ad, q1.y);
            }
        }
        if (kt < 7) stsB(cur ^ 1);
        CP_WAIT0();
        __syncthreads();
    }

    // --- epilogue: out[b, (tn0+n)*64 + ii] = acc + bias ---
    float bv[8];
#pragma unroll
    for (int n = 0; n < 8; n++) bv[n] = bias[(tn0 + n) * 64 + ii];

#pragma unroll
    for (int m = 0; m < 8; m++) {
        float* op = out + (size_t)(row0 + tm0 + m) * 4096 + ii;
        float2 p0 = unpack2(acc[m][0]);
        float2 p1 = unpack2(acc[m][1]);
        float2 p2 = unpack2(acc[m][2]);
        float2 p3 = unpack2(acc[m][3]);
        op[(tn0 + 0) * 64] = p0.x + bv[0];
        op[(tn0 + 1) * 64] = p0.y + bv[1];
        op[(tn0 + 2) * 64] = p1.x + bv[2];
        op[(tn0 + 3) * 64] = p1.y + bv[3];
        op[(tn0 + 4) * 64] = p2.x + bv[4];
        op[(tn0 + 5) * 64] = p2.y + bv[5];
        op[(tn0 + 6) * 64] = p3.x + bv[6];
        op[(tn0 + 7) * 64] = p3.y + bv[7];
    }
}

extern "C" void kernel_launch(void* const* d_in, const int* in_sizes, int n_in,
                              void* d_out, int out_size) {
    const float* x    = (const float*)d_in[0];  // (8192, 4096)
    const float* c0   = (const float*)d_in[1];  // (64,64,64,4,1)
    const float* c1   = (const float*)d_in[2];  // (64,64,64,1,4)
    const float* bias = (const float*)d_in[3];  // (4096,)
    float* out = (float*)d_out;                 // (8192, 4096)

    cudaFuncSetAttribute(s1_kernel, cudaFuncAttributeMaxDynamicSharedMemorySize, S1_SMEM);
    cudaFuncSetAttribute(s2_kernel, cudaFuncAttributeMaxDynamicSharedMemorySize, S2_SMEM);

    s1_kernel<<<dim3(2, 64, 64), 256, S1_SMEM>>>(x, c0);
    s2_kernel<<<dim3(64, 32), 256, S2_SMEM>>>(c1, bias, out);
}

// round 10
// speedup vs baseline: 1.6059x; 1.1866x over previous
#include <cuda_runtime.h>
#include <cuda_bf16.h>
#include <cstdint>

// BTT forward via mma.sync bf16 (HMMA, baseline PTX — no 'a'-target features),
// 3-term hi/lo split expressed as K-extension:
//   A_ext = [Ahi | Alo | Ahi],  B_ext = [Bhi | Bhi | Blo]  (K -> 3K)
//   => C = Ahi*Bhi + Alo*Bhi + Ahi*Blo   (error ~2^-16, << 1e-3)
//
// Stage 1 (CTA=(ntile,mtile,j)): D[128 b][128 n] = X[128][64] @ W0_j[64][256]-half
//   Z stored transposed+packed: g_Z[row][b] = {bf16hi<<16|bf16lo},
//   row = (n>>2)*256 + j*4 + (n&3)  ( = i'*256 + x'*4 + a in stage-2 view)
// Stage 2 (CTA=(ii,mtile)): D[128 b][64 y] = Zpanel[128][256] @ W1_ii[256][64]
//   K processed in 4 chunks of 64 real k (192 ext each), fp32 reg accumulate.

__device__ unsigned int g_Z[(size_t)16384 * 8192];  // 512 MiB packed hi/lo

// ---------------------------------------------------------------------------
__device__ __forceinline__ uint32_t smem_u32(const void* p) {
    return (uint32_t)__cvta_generic_to_shared(p);
}
__device__ __forceinline__ void ldsm_x4(uint32_t* r, uint32_t addr) {
    asm volatile("ldmatrix.sync.aligned.m8n8.x4.shared.b16 {%0,%1,%2,%3}, [%4];"
                 : "=r"(r[0]), "=r"(r[1]), "=r"(r[2]), "=r"(r[3]) : "r"(addr));
}
__device__ __forceinline__ void ldsm_x4_t(uint32_t* r, uint32_t addr) {
    asm volatile("ldmatrix.sync.aligned.m8n8.x4.trans.shared.b16 {%0,%1,%2,%3}, [%4];"
                 : "=r"(r[0]), "=r"(r[1]), "=r"(r[2]), "=r"(r[3]) : "r"(addr));
}
__device__ __forceinline__ void mma_bf16(float* c, const uint32_t* a, const uint32_t* b) {
    asm volatile("mma.sync.aligned.m16n8k16.row.col.f32.bf16.bf16.f32 "
                 "{%0,%1,%2,%3}, {%4,%5,%6,%7}, {%8,%9}, {%0,%1,%2,%3};"
                 : "+f"(c[0]), "+f"(c[1]), "+f"(c[2]), "+f"(c[3])
                 : "r"(a[0]), "r"(a[1]), "r"(a[2]), "r"(a[3]), "r"(b[0]), "r"(b[1]));
}

__device__ __forceinline__ uint32_t pack_hilo(float v) {
    __nv_bfloat16 h = __float2bfloat16(v);
    float r = v - __bfloat162float(h);
    __nv_bfloat16 l = __float2bfloat16(r);
    return ((uint32_t)__bfloat16_as_ushort(h) << 16) | (uint32_t)__bfloat16_as_ushort(l);
}
// float4 -> 4 hi bf16 (uint2) + 4 lo bf16 (uint2), element i at half-word i
__device__ __forceinline__ void split4(float4 v, uint2& hip, uint2& lop) {
    uint32_t p0 = pack_hilo(v.x), p1 = pack_hilo(v.y);
    uint32_t p2 = pack_hilo(v.z), p3 = pack_hilo(v.w);
    hip.x = (p0 >> 16) | (p1 & 0xFFFF0000u);
    hip.y = (p2 >> 16) | (p3 & 0xFFFF0000u);
    lop.x = (p0 & 0xFFFFu) | (p1 << 16);
    lop.y = (p2 & 0xFFFFu) | (p3 << 16);
}

// ---------------------------------------------------------------------------
// Stage 1: tile M=128(b) x N=128(n), K_ext=192. 256 thr = 8 warps (2m x 4n),
// warp tile 64x32. smem: A[m][kext] stride 200 halves (400B),
//                        B[kext][n] stride 136 halves (272B), ldmatrix.trans.
// ---------------------------------------------------------------------------
#define S1_A_STRIDE 400  /* bytes */
#define S1_B_STRIDE 272
#define S1_B_OFF    51200
#define S1_SMEM     (51200 + 52224)

__global__ void __launch_bounds__(256, 2) s1_kernel(const float* __restrict__ x,
                                                    const float* __restrict__ c0) {
    extern __shared__ char sm[];
    char* smA = sm;
    char* smB = sm + S1_B_OFF;
    const uint32_t sbA = smem_u32(smA), sbB = smem_u32(smB);

    const int tid = threadIdx.x, wid = tid >> 5, lane = tid & 31;
    const int col0 = blockIdx.x * 128;
    const int row0 = blockIdx.y * 128;
    const int j    = blockIdx.z;

    // --- A: X[128 b][64 k] -> ext [m][hi|lo|hi] ---
    {
        const int m = tid >> 1, kh = tid & 1;  // 2 thr/row, 8 float4 each
        const float* src = x + (size_t)(row0 + m) * 4096 + j * 64 + kh * 32;
        char* dst = smA + m * S1_A_STRIDE;
#pragma unroll
        for (int q = 0; q < 8; q++) {
            float4 v = *reinterpret_cast<const float4*>(src + q * 4);
            uint2 hp, lp;
            split4(v, hp, lp);
            const int k = kh * 32 + q * 4;
            *reinterpret_cast<uint2*>(dst + k * 2)         = hp;  // seg0 hi
            *reinterpret_cast<uint2*>(dst + (64 + k) * 2)  = lp;  // seg1 lo
            *reinterpret_cast<uint2*>(dst + (128 + k) * 2) = hp;  // seg2 hi
        }
    }
    // --- B: W0_j rows (x-major, n coalesced) -> ext [hi|hi|lo][n] ---
    {
        const int xr = tid >> 2, nq = tid & 3;  // 4 thr/row, 8 float4 each
        const float* src = c0 + (size_t)j * 16384 + (size_t)xr * 256 + col0;
#pragma unroll
        for (int q = 0; q < 8; q++) {
            const int n = (nq * 8 + q) * 4;
            float4 v = *reinterpret_cast<const float4*>(src + n);
            uint2 hp, lp;
            split4(v, hp, lp);
            *reinterpret_cast<uint2*>(smB + xr * S1_B_STRIDE + n * 2)         = hp;
            *reinterpret_cast<uint2*>(smB + (64 + xr) * S1_B_STRIDE + n * 2)  = hp;
            *reinterpret_cast<uint2*>(smB + (128 + xr) * S1_B_STRIDE + n * 2) = lp;
        }
    }
    __syncthreads();

    const int mw = (wid & 1) * 64;
    const int nw = (wid >> 1) * 32;

    float acc[4][4][4];
#pragma unroll
    for (int mi = 0; mi < 4; mi++)
#pragma unroll
        for (int ni = 0; ni < 4; ni++)
#pragma unroll
            for (int r = 0; r < 4; r++) acc[mi][ni][r] = 0.f;

    // per-lane ldmatrix base addresses
    uint32_t aAddr[4], bAddr[2];
#pragma unroll
    for (int mi = 0; mi < 4; mi++)
        aAddr[mi] = sbA + (mw + mi * 16 + (lane & 15)) * S1_A_STRIDE + ((lane >> 4) * 8) * 2;
#pragma unroll
    for (int nj = 0; nj < 2; nj++)
        bAddr[nj] = sbB + (lane & 15) * S1_B_STRIDE + (nw + nj * 16 + (lane >> 4) * 8) * 2;

#pragma unroll 2
    for (int ks = 0; ks < 12; ks++) {
        uint32_t af[4][4], bf[2][4];
#pragma unroll
        for (int mi = 0; mi < 4; mi++) ldsm_x4(af[mi], aAddr[mi] + ks * 32);
#pragma unroll
        for (int nj = 0; nj < 2; nj++) ldsm_x4_t(bf[nj], bAddr[nj] + ks * 16 * S1_B_STRIDE);
#pragma unroll
        for (int mi = 0; mi < 4; mi++)
#pragma unroll
            for (int nj = 0; nj < 2; nj++) {
                mma_bf16(acc[mi][nj * 2],     af[mi], &bf[nj][0]);
                mma_bf16(acc[mi][nj * 2 + 1], af[mi], &bf[nj][2]);
            }
    }

    // --- epilogue: packed transposed store to g_Z ---
#pragma unroll
    for (int mi = 0; mi < 4; mi++)
#pragma unroll
        for (int ni = 0; ni < 4; ni++) {
            const int m = mw + mi * 16 + (lane >> 2);
            const int n = col0 + nw + ni * 8 + (lane & 3) * 2;
#pragma unroll
            for (int r = 0; r < 4; r++) {
                const int mm = m + (r >> 1) * 8;         // c2,c3 -> +8 rows
                const int nn = n + (r & 1);              // c1,c3 -> +1 col
                const size_t zrow = (size_t)(nn >> 2) * 256 + j * 4 + (nn & 3);
                g_Z[zrow * 8192 + row0 + mm] = pack_hilo(acc[mi][ni][r]);
            }
        }
}

// ---------------------------------------------------------------------------
// Stage 2: tile M=128(b) x N=64(y), K=256 real in 4 chunks of 64 (192 ext).
// 256 thr = 8 warps (4m x 2n), warp tile 32x32.
// smem: A[m][kext] stride 400B; B[y][kext] stride 400B (non-trans ldmatrix).
// ---------------------------------------------------------------------------
#define S2_STRIDE 400
#define S2_B_OFF  51200
#define S2_SMEM   (51200 + 25600)

__global__ void __launch_bounds__(256, 2) s2_kernel(const float* __restrict__ c1,
                                                    const float* __restrict__ bias,
                                                    float* __restrict__ out) {
    extern __shared__ char sm[];
    char* smA = sm;
    char* smB = sm + S2_B_OFF;
    const uint32_t sbA = smem_u32(smA), sbB = smem_u32(smB);

    const int tid = threadIdx.x, wid = tid >> 5, lane = tid & 31;
    const int ii   = blockIdx.x;
    const int row0 = blockIdx.y * 128;

    const int mw = (wid & 3) * 32;
    const int nw = (wid >> 2) * 32;

    float acc[2][4][4];
#pragma unroll
    for (int mi = 0; mi < 2; mi++)
#pragma unroll
        for (int n8 = 0; n8 < 4; n8++)
#pragma unroll
            for (int r = 0; r < 4; r++) acc[mi][n8][r] = 0.f;

    uint32_t aAddr[2], bAddr[2];
#pragma unroll
    for (int mi = 0; mi < 2; mi++)
        aAddr[mi] = sbA + (mw + mi * 16 + (lane & 15)) * S2_STRIDE + ((lane >> 4) * 8) * 2;
#pragma unroll
    for (int nj = 0; nj < 2; nj++)
        bAddr[nj] = sbB + (nw + nj * 16 + ((lane >> 4) << 3) + (lane & 7)) * S2_STRIDE
                        + (((lane >> 3) & 1) * 8) * 2;

#pragma unroll 1
    for (int kc = 0; kc < 4; kc++) {
        // --- A: g_Z packed [k][b] -> [b][hi|lo|hi], register transpose ---
        {
            const int b = tid & 127, grp = tid >> 7;
            char* dst = smA + b * S2_STRIDE;
#pragma unroll
            for (int q = 0; q < 4; q++) {
                const int k8 = (grp * 4 + q) * 8;
                const unsigned int* zp =
                    g_Z + (size_t)(ii * 256 + kc * 64 + k8) * 8192 + row0 + b;
                uint32_t u[8];
#pragma unroll
                for (int i = 0; i < 8; i++) u[i] = zp[(size_t)i * 8192];
                uint4 hv, lv;
                hv.x = (u[0] >> 16) | (u[1] & 0xFFFF0000u);
                hv.y = (u[2] >> 16) | (u[3] & 0xFFFF0000u);
                hv.z = (u[4] >> 16) | (u[5] & 0xFFFF0000u);
                hv.w = (u[6] >> 16) | (u[7] & 0xFFFF0000u);
                lv.x = (u[0] & 0xFFFFu) | (u[1] << 16);
                lv.y = (u[2] & 0xFFFFu) | (u[3] << 16);
                lv.z = (u[4] & 0xFFFFu) | (u[5] << 16);
                lv.w = (u[6] & 0xFFFFu) | (u[7] << 16);
                *reinterpret_cast<uint4*>(dst + k8 * 2)         = hv;  // seg0 hi
                *reinterpret_cast<uint4*>(dst + (64 + k8) * 2)  = lv;  // seg1 lo
                *reinterpret_cast<uint4*>(dst + (128 + k8) * 2) = hv;  // seg2 hi
            }
        }
        // --- B: W1 gather -> [y][hi|hi|lo], k = xl*4+a contiguous per float4 ---
        {
            const int y = tid >> 2, xq = tid & 3;
            char* dst = smB + y * S2_STRIDE;
#pragma unroll
            for (int q = 0; q < 4; q++) {
                const int xl = xq * 4 + q;  // 0..15
                float4 v = *reinterpret_cast<const float4*>(
                    c1 + (size_t)(kc * 16 + xl) * 16384 + (size_t)y * 256 + ii * 4);
                uint2 hp, lp;
                split4(v, hp, lp);
                const int k = xl * 4;
                *reinterpret_cast<uint2*>(dst + k * 2)         = hp;
                *reinterpret_cast<uint2*>(dst + (64 + k) * 2)  = hp;
                *reinterpret_cast<uint2*>(dst + (128 + k) * 2) = lp;
            }
        }
        __syncthreads();

#pragma unroll 2
        for (int ks = 0; ks < 12; ks++) {
            uint32_t af[2][4], bf[2][4];
#pragma unroll
            for (int mi = 0; mi < 2; mi++) ldsm_x4(af[mi], aAddr[mi] + ks * 32);
#pragma unroll
            for (int nj = 0; nj < 2; nj++) ldsm_x4(bf[nj], bAddr[nj] + ks * 32);
#pragma unroll
            for (int mi = 0; mi < 2; mi++)
#pragma unroll
                for (int nj = 0; nj < 2; nj++) {
                    mma_bf16(acc[mi][nj * 2],     af[mi], &bf[nj][0]);
                    mma_bf16(acc[mi][nj * 2 + 1], af[mi], &bf[nj][2]);
                }
        }
        __syncthreads();
    }

    // --- epilogue: out[b][y*64+ii] = acc + bias[y*64+ii] ---
#pragma unroll
    for (int mi = 0; mi < 2; mi++)
#pragma unroll
        for (int n8 = 0; n8 < 4; n8++) {
            const int m = mw + mi * 16 + (lane >> 2);
            const int y = nw + n8 * 8 + (lane & 3) * 2;
#pragma unroll
            for (int r = 0; r < 4; r++) {
                const int mm = m + (r >> 1) * 8;
                const int yy = y + (r & 1);
                out[(size_t)(row0 + mm) * 4096 + yy * 64 + ii] =
                    acc[mi][n8][r] + bias[yy * 64 + ii];
            }
        }
}

extern "C" void kernel_launch(void* const* d_in, const int* in_sizes, int n_in,
                              void* d_out, int out_size) {
    const float* x    = (const float*)d_in[0];  // (8192, 4096)
    const float* c0   = (const float*)d_in[1];  // (64,64,64,4,1)
    const float* c1   = (const float*)d_in[2];  // (64,64,64,1,4)
    const float* bias = (const float*)d_in[3];  // (4096,)
    float* out = (float*)d_out;                 // (8192, 4096)

    cudaFuncSetAttribute(s1_kernel, cudaFuncAttributeMaxDynamicSharedMemorySize, S1_SMEM);
    cudaFuncSetAttribute(s2_kernel, cudaFuncAttributeMaxDynamicSharedMemorySize, S2_SMEM);

    s1_kernel<<<dim3(2, 64, 64), 256, S1_SMEM>>>(x, c0);      // (ntile, mtile, j)
    s2_kernel<<<dim3(64, 64), 256, S2_SMEM>>>(c1, bias, out); // (ii, mtile)
}

// round 11
// speedup vs baseline: 1.6328x; 1.0167x over previous
#include <cuda_runtime.h>
#include <cuda_bf16.h>
#include <cstdint>

// BTT forward via mma.sync bf16 (HMMA, baseline PTX).
// Stage 1: 3-term hi/lo split as K-extension (dedup'd smem segments).
// Stage 2: hi/lo interleaved along the MMA m-dimension; A tiles are raw
//          packed-u32 g_Z copied via cp.async (no conversion), Kext=[Bhi|Blo],
//          epilogue merges m-pairs with shfl_xor(4) (includes AloBlo term).

__device__ unsigned int g_Z[(size_t)16384 * 8192];  // 512 MiB packed {hi<<16|lo}

// ---------------------------------------------------------------------------
__device__ __forceinline__ uint32_t smem_u32(const void* p) {
    return (uint32_t)__cvta_generic_to_shared(p);
}
__device__ __forceinline__ void ldsm_x4(uint32_t* r, uint32_t addr) {
    asm volatile("ldmatrix.sync.aligned.m8n8.x4.shared.b16 {%0,%1,%2,%3}, [%4];"
                 : "=r"(r[0]), "=r"(r[1]), "=r"(r[2]), "=r"(r[3]) : "r"(addr));
}
__device__ __forceinline__ void ldsm_x4_t(uint32_t* r, uint32_t addr) {
    asm volatile("ldmatrix.sync.aligned.m8n8.x4.trans.shared.b16 {%0,%1,%2,%3}, [%4];"
                 : "=r"(r[0]), "=r"(r[1]), "=r"(r[2]), "=r"(r[3]) : "r"(addr));
}
__device__ __forceinline__ void mma_bf16(float* c, const uint32_t* a, const uint32_t* b) {
    asm volatile("mma.sync.aligned.m16n8k16.row.col.f32.bf16.bf16.f32 "
                 "{%0,%1,%2,%3}, {%4,%5,%6,%7}, {%8,%9}, {%0,%1,%2,%3};"
                 : "+f"(c[0]), "+f"(c[1]), "+f"(c[2]), "+f"(c[3])
                 : "r"(a[0]), "r"(a[1]), "r"(a[2]), "r"(a[3]), "r"(b[0]), "r"(b[1]));
}
__device__ __forceinline__ void cp16(uint32_t dst, const void* src) {
    asm volatile("cp.async.cg.shared.global [%0], [%1], 16;" :: "r"(dst), "l"(src));
}
#define CP_COMMIT()  asm volatile("cp.async.commit_group;")
#define CP_WAIT(n)   asm volatile("cp.async.wait_group %0;" :: "n"(n))

__device__ __forceinline__ uint32_t pack_hilo(float v) {
    __nv_bfloat16 h = __float2bfloat16(v);
    float r = v - __bfloat162float(h);
    __nv_bfloat16 l = __float2bfloat16(r);
    return ((uint32_t)__bfloat16_as_ushort(h) << 16) | (uint32_t)__bfloat16_as_ushort(l);
}
__device__ __forceinline__ void split4(float4 v, uint2& hip, uint2& lop) {
    uint32_t p0 = pack_hilo(v.x), p1 = pack_hilo(v.y);
    uint32_t p2 = pack_hilo(v.z), p3 = pack_hilo(v.w);
    hip.x = (p0 >> 16) | (p1 & 0xFFFF0000u);
    hip.y = (p2 >> 16) | (p3 & 0xFFFF0000u);
    lop.x = (p0 & 0xFFFFu) | (p1 << 16);
    lop.y = (p2 & 0xFFFFu) | (p3 << 16);
}

// ---------------------------------------------------------------------------
// Stage 1: tile M=128(b) x N=128(n), K_ext=192 via dedup'd [hi|lo] segments.
// 8 warps (2m x 4n), warp tile 64x32.
// smem: A[m 128][128 hw: hi|lo] stride 272B; B[128 rows: hi|lo][n 128] stride 272B.
// ---------------------------------------------------------------------------
#define S1_STRIDE 272
#define S1_B_OFF  34816
#define S1_SMEM   69632

__global__ void __launch_bounds__(256, 2) s1_kernel(const float* __restrict__ x,
                                                    const float* __restrict__ c0) {
    extern __shared__ char sm[];
    char* smA = sm;
    char* smB = sm + S1_B_OFF;
    const uint32_t sbA = smem_u32(smA), sbB = smem_u32(smB);

    const int tid = threadIdx.x, wid = tid >> 5, lane = tid & 31;
    const int col0 = blockIdx.x * 128;
    const int row0 = blockIdx.y * 128;
    const int j    = blockIdx.z;

    // --- A: X[128 b][64 k] -> [m][hi(64)|lo(64)] ---
    {
        const int m = tid >> 1, kh = tid & 1;
        const float* src = x + (size_t)(row0 + m) * 4096 + j * 64 + kh * 32;
        char* dst = smA + m * S1_STRIDE;
#pragma unroll
        for (int q = 0; q < 8; q++) {
            float4 v = *reinterpret_cast<const float4*>(src + q * 4);
            uint2 hp, lp;
            split4(v, hp, lp);
            const int k = kh * 32 + q * 4;
            *reinterpret_cast<uint2*>(dst + k * 2)        = hp;
            *reinterpret_cast<uint2*>(dst + (64 + k) * 2) = lp;
        }
    }
    // --- B: W0_j rows -> [hi rows 0-63 | lo rows 64-127][n] ---
    {
        const int xr = tid >> 2, nq = tid & 3;
        const float* src = c0 + (size_t)j * 16384 + (size_t)xr * 256 + col0;
#pragma unroll
        for (int q = 0; q < 8; q++) {
            const int n = (nq * 8 + q) * 4;
            float4 v = *reinterpret_cast<const float4*>(src + n);
            uint2 hp, lp;
            split4(v, hp, lp);
            *reinterpret_cast<uint2*>(smB + xr * S1_STRIDE + n * 2)        = hp;
            *reinterpret_cast<uint2*>(smB + (64 + xr) * S1_STRIDE + n * 2) = lp;
        }
    }
    __syncthreads();

    const int mw = (wid & 1) * 64;
    const int nw = (wid >> 1) * 32;

    float acc[4][4][4];
#pragma unroll
    for (int mi = 0; mi < 4; mi++)
#pragma unroll
        for (int ni = 0; ni < 4; ni++)
#pragma unroll
            for (int r = 0; r < 4; r++) acc[mi][ni][r] = 0.f;

    uint32_t aAddr[4], bAddr[2];
#pragma unroll
    for (int mi = 0; mi < 4; mi++)
        aAddr[mi] = sbA + (mw + mi * 16 + (lane & 15)) * S1_STRIDE + ((lane >> 4) * 8) * 2;
#pragma unroll
    for (int nj = 0; nj < 2; nj++)
        bAddr[nj] = sbB + (lane & 15) * S1_STRIDE + (nw + nj * 16 + (lane >> 4) * 8) * 2;

    // ks: seg s = ks>>2 (A: 0=hi,1=lo,2=hi ; B: 0=hi,1=hi,2=lo), q = ks&3
#pragma unroll 2
    for (int ks = 0; ks < 12; ks++) {
        const int s = ks >> 2, q = ks & 3;
        const int aoff = ((s == 1 ? 64 : 0) + q * 16) * 2;
        const int brow = (s == 2 ? 64 : 0) + q * 16;
        uint32_t af[4][4], bf[2][4];
#pragma unroll
        for (int mi = 0; mi < 4; mi++) ldsm_x4(af[mi], aAddr[mi] + aoff);
#pragma unroll
        for (int nj = 0; nj < 2; nj++) ldsm_x4_t(bf[nj], bAddr[nj] + brow * S1_STRIDE);
#pragma unroll
        for (int mi = 0; mi < 4; mi++)
#pragma unroll
            for (int nj = 0; nj < 2; nj++) {
                mma_bf16(acc[mi][nj * 2],     af[mi], &bf[nj][0]);
                mma_bf16(acc[mi][nj * 2 + 1], af[mi], &bf[nj][2]);
            }
    }

    // --- epilogue: packed transposed store to g_Z ---
#pragma unroll
    for (int mi = 0; mi < 4; mi++)
#pragma unroll
        for (int ni = 0; ni < 4; ni++) {
            const int m = mw + mi * 16 + (lane >> 2);
            const int n = col0 + nw + ni * 8 + (lane & 3) * 2;
#pragma unroll
            for (int r = 0; r < 4; r++) {
                const int mm = m + (r >> 1) * 8;
                const int nn = n + (r & 1);
                const size_t zrow = (size_t)(nn >> 2) * 256 + j * 4 + (nn & 3);
                g_Z[zrow * 8192 + row0 + mm] = pack_hilo(acc[mi][ni][r]);
            }
        }
}

// ---------------------------------------------------------------------------
// Stage 2: tile b=64 (m_hw=128 interleaved lo/hi) x N=64(y), K=256 real
// in 4 chunks of 64, Kext = [Bhi|Blo] per chunk. 8 warps (4m x 2n),
// warp tile 32hw x 32y. A: raw g_Z u32 via cp.async double-buffered,
// frags via ldmatrix.trans. B: LDG-prefetch + split4 + STS, single buffer.
// smem: A 2 x [k 64][256B] stride 272; B [y 64][hi 128B | lo 128B] stride 272.
// ---------------------------------------------------------------------------
#define S2_STRIDE 272
#define S2_ABUF   17408
#define S2_B_OFF  34816
#define S2_SMEM   52224

__global__ void __launch_bounds__(256, 2) s2_kernel(const float* __restrict__ c1,
                                                    const float* __restrict__ bias,
                                                    float* __restrict__ out) {
    extern __shared__ char sm[];
    char* smB = sm + S2_B_OFF;
    const uint32_t sbA = smem_u32(sm), sbB = smem_u32(smB);

    const int tid = threadIdx.x, wid = tid >> 5, lane = tid & 31;
    const int ii    = blockIdx.x;
    const int row0b = blockIdx.y * 64;

    const int mw = (wid & 3) * 32;   // warp m_hw tile (32 halfwords = 16 b)
    const int nw = (wid >> 2) * 32;  // warp y tile

    // A cp.async mapping: thr -> row k = tid>>2, 4 x 16B chunks c = (tid&3)+q*4
    const int ak = tid >> 2, ac = tid & 3;
    const unsigned int* a_src0 = g_Z + (size_t)(ii * 256 + ak) * 8192 + row0b + ac * 4;
    const uint32_t a_dst0 = sbA + ak * S2_STRIDE + ac * 16;

    // B mapping: thr -> y = tid>>2, xl = (tid&3) + q*4
    const int by = tid >> 2, bq = tid & 3;
    float4 breg[4];

    auto cpA = [&](int kc, int buf) {
        const unsigned int* src = a_src0 + (size_t)(kc * 64) * 8192;
        const uint32_t dst = a_dst0 + buf * S2_ABUF;
#pragma unroll
        for (int q = 0; q < 4; q++)
            cp16(dst + q * 64, src + q * 16);
        CP_COMMIT();
    };
    auto ldgB = [&](int kc) {
#pragma unroll
        for (int q = 0; q < 4; q++) {
            const int xl = bq + q * 4;
            breg[q] = *reinterpret_cast<const float4*>(
                c1 + (size_t)(kc * 16 + xl) * 16384 + (size_t)by * 256 + ii * 4);
        }
    };
    auto stsB = [&]() {
        char* dst = smB + by * S2_STRIDE;
#pragma unroll
        for (int q = 0; q < 4; q++) {
            const int xl = bq + q * 4;
            uint2 hp, lp;
            split4(breg[q], hp, lp);
            *reinterpret_cast<uint2*>(dst + xl * 8)       = hp;
            *reinterpret_cast<uint2*>(dst + 128 + xl * 8) = lp;
        }
    };

    float acc[2][4][4];
#pragma unroll
    for (int mi = 0; mi < 2; mi++)
#pragma unroll
        for (int n8 = 0; n8 < 4; n8++)
#pragma unroll
            for (int r = 0; r < 4; r++) acc[mi][n8][r] = 0.f;

    uint32_t aAddr[2], bAddr[2];
#pragma unroll
    for (int mi = 0; mi < 2; mi++)
        aAddr[mi] = sbA + (lane & 15) * S2_STRIDE + (mw + mi * 16 + (lane >> 4) * 8) * 2;
#pragma unroll
    for (int nj = 0; nj < 2; nj++)
        bAddr[nj] = sbB + (nw + nj * 16 + ((lane >> 4) << 3) + (lane & 7)) * S2_STRIDE
                        + (((lane >> 3) & 1) * 8) * 2;

    // prologue
    cpA(0, 0);
    ldgB(0);

#pragma unroll 1
    for (int kc = 0; kc < 4; kc++) {
        const int buf = kc & 1;
        if (kc < 3) cpA(kc + 1, buf ^ 1);
        stsB();
        if (kc < 3) ldgB(kc + 1);
        if (kc < 3) { CP_WAIT(1); } else { CP_WAIT(0); }
        __syncthreads();

        const uint32_t aBase = buf * S2_ABUF;
#pragma unroll
        for (int s = 0; s < 2; s++)
#pragma unroll
            for (int q = 0; q < 4; q++) {
                uint32_t t[2][4], bf[2][4];
#pragma unroll
                for (int mi = 0; mi < 2; mi++)
                    ldsm_x4_t(t[mi], aAddr[mi] + aBase + q * 16 * S2_STRIDE);
#pragma unroll
                for (int nj = 0; nj < 2; nj++)
                    ldsm_x4(bf[nj], bAddr[nj] + (s * 64 + q * 16) * 2);
#pragma unroll
                for (int mi = 0; mi < 2; mi++) {
                    uint32_t af[4] = {t[mi][0], t[mi][2], t[mi][1], t[mi][3]};
#pragma unroll
                    for (int nj = 0; nj < 2; nj++) {
                        mma_bf16(acc[mi][nj * 2],     af, &bf[nj][0]);
                        mma_bf16(acc[mi][nj * 2 + 1], af, &bf[nj][2]);
                    }
                }
            }
        __syncthreads();
    }

    // --- epilogue: merge lo/hi m-pairs via shfl_xor(4), add bias, store ---
    const int r = lane >> 2;
#pragma unroll
    for (int mi = 0; mi < 2; mi++)
#pragma unroll
        for (int n8 = 0; n8 < 4; n8++) {
            float o[4];
#pragma unroll
            for (int c = 0; c < 4; c++) {
                float v = acc[mi][n8][c];
                o[c] = v + __shfl_xor_sync(0xFFFFFFFFu, v, 4);
            }
            if ((lane & 4) == 0) {
                const int bl = row0b + ((mw + mi * 16 + r) >> 1);
                const int y0 = nw + n8 * 8 + 2 * (lane & 3);
                out[(size_t)bl * 4096 + y0 * 64 + ii]         = o[0] + bias[y0 * 64 + ii];
                out[(size_t)bl * 4096 + (y0 + 1) * 64 + ii]   = o[1] + bias[(y0 + 1) * 64 + ii];
                out[(size_t)(bl + 4) * 4096 + y0 * 64 + ii]   = o[2] + bias[y0 * 64 + ii];
                out[(size_t)(bl + 4) * 4096 + (y0 + 1) * 64 + ii] = o[3] + bias[(y0 + 1) * 64 + ii];
            }
        }
}

extern "C" void kernel_launch(void* const* d_in, const int* in_sizes, int n_in,
                              void* d_out, int out_size) {
    const float* x    = (const float*)d_in[0];  // (8192, 4096)
    const float* c0   = (const float*)d_in[1];  // (64,64,64,4,1)
    const float* c1   = (const float*)d_in[2];  // (64,64,64,1,4)
    const float* bias = (const float*)d_in[3];  // (4096,)
    float* out = (float*)d_out;                 // (8192, 4096)

    cudaFuncSetAttribute(s1_kernel, cudaFuncAttributeMaxDynamicSharedMemorySize, S1_SMEM);
    cudaFuncSetAttribute(s2_kernel, cudaFuncAttributeMaxDynamicSharedMemorySize, S2_SMEM);

    s1_kernel<<<dim3(2, 64, 64), 256, S1_SMEM>>>(x, c0);       // (ntile, mtile, j)
    s2_kernel<<<dim3(64, 128), 256, S2_SMEM>>>(c1, bias, out); // (ii, mtile)
}

// round 12
// speedup vs baseline: 1.6468x; 1.0086x over previous
#include <cuda_runtime.h>
#include <cuda_bf16.h>
#include <cstdint>

// BTT forward via mma.sync bf16 (HMMA, baseline PTX), 3-term hi/lo split as
// K-extension with dedup'd smem segments:
//   A segs {hi, lo, hi}  x  B segs {hi, hi, lo}
// Weights are pre-converted once into GEMM-ready bf16 images (w0e, w1e).
// Intermediate Z kept as two bf16 planes (hi, lo), b-contiguous -> s2 is pure
// cp.async. s2 writes transposed g_O[(y*64+ii)][b] (coalesced); a final
// transpose kernel emits out[b][col] + bias.

__device__ __nv_bfloat16 g_Zhi[(size_t)16384 * 8192];  // 256 MiB
__device__ __nv_bfloat16 g_Zlo[(size_t)16384 * 8192];  // 256 MiB
__device__ __nv_bfloat16 g_w0e[64 * 256 * 128];        // 4 MiB  [j][n][hi64|lo64]
__device__ __nv_bfloat16 g_w1e[64 * 64 * 512];         // 4 MiB  [ii][y][kc4][hi64|lo64]
__device__ float        g_O[(size_t)4096 * 8192];      // 128 MiB [(y*64+ii)][b]

// ---------------------------------------------------------------------------
__device__ __forceinline__ uint32_t smem_u32(const void* p) {
    return (uint32_t)__cvta_generic_to_shared(p);
}
__device__ __forceinline__ void ldsm_x4(uint32_t* r, uint32_t addr) {
    asm volatile("ldmatrix.sync.aligned.m8n8.x4.shared.b16 {%0,%1,%2,%3}, [%4];"
                 : "=r"(r[0]), "=r"(r[1]), "=r"(r[2]), "=r"(r[3]) : "r"(addr));
}
__device__ __forceinline__ void ldsm_x4_t(uint32_t* r, uint32_t addr) {
    asm volatile("ldmatrix.sync.aligned.m8n8.x4.trans.shared.b16 {%0,%1,%2,%3}, [%4];"
                 : "=r"(r[0]), "=r"(r[1]), "=r"(r[2]), "=r"(r[3]) : "r"(addr));
}
__device__ __forceinline__ void mma_bf16(float* c, const uint32_t* a, const uint32_t* b) {
    asm volatile("mma.sync.aligned.m16n8k16.row.col.f32.bf16.bf16.f32 "
                 "{%0,%1,%2,%3}, {%4,%5,%6,%7}, {%8,%9}, {%0,%1,%2,%3};"
                 : "+f"(c[0]), "+f"(c[1]), "+f"(c[2]), "+f"(c[3])
                 : "r"(a[0]), "r"(a[1]), "r"(a[2]), "r"(a[3]), "r"(b[0]), "r"(b[1]));
}
__device__ __forceinline__ void cp16(uint32_t dst, const void* src) {
    asm volatile("cp.async.cg.shared.global [%0], [%1], 16;" :: "r"(dst), "l"(src));
}
#define CP_COMMIT()  asm volatile("cp.async.commit_group;")
#define CP_WAIT(n)   asm volatile("cp.async.wait_group %0;" :: "n"(n))

__device__ __forceinline__ void split1(float v, __nv_bfloat16& h, __nv_bfloat16& l) {
    h = __float2bfloat16(v);
    l = __float2bfloat16(v - __bfloat162float(h));
}
__device__ __forceinline__ uint32_t pack_hilo(float v) {
    __nv_bfloat16 h, l;
    split1(v, h, l);
    return ((uint32_t)__bfloat16_as_ushort(h) << 16) | (uint32_t)__bfloat16_as_ushort(l);
}
__device__ __forceinline__ void split4(float4 v, uint2& hip, uint2& lop) {
    uint32_t p0 = pack_hilo(v.x), p1 = pack_hilo(v.y);
    uint32_t p2 = pack_hilo(v.z), p3 = pack_hilo(v.w);
    hip.x = (p0 >> 16) | (p1 & 0xFFFF0000u);
    hip.y = (p2 >> 16) | (p3 & 0xFFFF0000u);
    lop.x = (p0 & 0xFFFFu) | (p1 << 16);
    lop.y = (p2 & 0xFFFFu) | (p3 << 16);
}

// ---------------------------------------------------------------------------
// Prep kernels: one-time weight conversion (outputs are L2-resident, 4 MiB each)
// ---------------------------------------------------------------------------
__global__ void prep0_kernel(const float* __restrict__ c0) {
    const int j = blockIdx.x, n = threadIdx.x;
    __nv_bfloat16* dst = g_w0e + ((size_t)j * 256 + n) * 128;
#pragma unroll 4
    for (int x = 0; x < 64; x++) {
        __nv_bfloat16 h, l;
        split1(c0[(size_t)j * 16384 + x * 256 + n], h, l);
        dst[x] = h;
        dst[64 + x] = l;
    }
}
__global__ void prep1_kernel(const float* __restrict__ c1) {
    const int xp = blockIdx.x, t = threadIdx.x;
    const int ii = t >> 2, a = t & 3;
    const int kc = xp >> 4, kl = (xp & 15) * 4 + a;
#pragma unroll 4
    for (int y = 0; y < 64; y++) {
        __nv_bfloat16 h, l;
        split1(c1[(size_t)xp * 16384 + y * 256 + t], h, l);
        __nv_bfloat16* dst = g_w1e + ((size_t)ii * 64 + y) * 512 + kc * 128;
        dst[kl] = h;
        dst[64 + kl] = l;
    }
}

// ---------------------------------------------------------------------------
// Stage 1: tile M=128(b) x N=128(n), Kext=192 via dedup'd [hi|lo] segments.
// 8 warps (2m x 4n), warp tile 64x32.
// smem: A[m 128][hi64|lo64 hw] stride 272; B[n 128][hi64|lo64 hw] stride 272.
// B comes straight from w0e via cp.async.
// ---------------------------------------------------------------------------
#define S1_STRIDE 272
#define S1_B_OFF  34816
#define S1_SMEM   69632

__global__ void __launch_bounds__(256, 2) s1_kernel(const float* __restrict__ x) {
    extern __shared__ char sm[];
    char* smA = sm;
    const uint32_t sbA = smem_u32(sm), sbB = sbA + S1_B_OFF;

    const int tid = threadIdx.x, wid = tid >> 5, lane = tid & 31;
    const int col0 = blockIdx.x * 128;
    const int row0 = blockIdx.y * 128;
    const int j    = blockIdx.z;

    // --- B: cp.async from w0e, rows n = col0..col0+127, 256B each ---
    {
        const int r = tid >> 1, c0b = (tid & 1) * 8;
        const char* src = reinterpret_cast<const char*>(
            g_w0e + ((size_t)j * 256 + col0 + r) * 128);
        const uint32_t dst = sbB + r * S1_STRIDE;
#pragma unroll
        for (int q = 0; q < 8; q++)
            cp16(dst + (c0b + q) * 16, src + (c0b + q) * 16);
        CP_COMMIT();
    }
    // --- A: X[128 b][64 k] -> [m][hi(64)|lo(64)] (overlaps with cp.async B) ---
    {
        const int m = tid >> 1, kh = tid & 1;
        const float* src = x + (size_t)(row0 + m) * 4096 + j * 64 + kh * 32;
        char* dst = smA + m * S1_STRIDE;
#pragma unroll
        for (int q = 0; q < 8; q++) {
            float4 v = *reinterpret_cast<const float4*>(src + q * 4);
            uint2 hp, lp;
            split4(v, hp, lp);
            const int k = kh * 32 + q * 4;
            *reinterpret_cast<uint2*>(dst + k * 2)        = hp;
            *reinterpret_cast<uint2*>(dst + (64 + k) * 2) = lp;
        }
    }
    CP_WAIT(0);
    __syncthreads();

    const int mw = (wid & 1) * 64;
    const int nw = (wid >> 1) * 32;

    float acc[4][4][4];
#pragma unroll
    for (int mi = 0; mi < 4; mi++)
#pragma unroll
        for (int ni = 0; ni < 4; ni++)
#pragma unroll
            for (int r = 0; r < 4; r++) acc[mi][ni][r] = 0.f;

    uint32_t aAddr[4], bAddr[2];
#pragma unroll
    for (int mi = 0; mi < 4; mi++)
        aAddr[mi] = sbA + (mw + mi * 16 + (lane & 15)) * S1_STRIDE + ((lane >> 4) * 8) * 2;
#pragma unroll
    for (int nj = 0; nj < 2; nj++)
        bAddr[nj] = sbB + (nw + nj * 16 + ((lane >> 4) << 3) + (lane & 7)) * S1_STRIDE
                        + (((lane >> 3) & 1) * 8) * 2;

    // s: A seg {hi,lo,hi}, B seg {hi,hi,lo}; q: k16 within 64
#pragma unroll 2
    for (int ks = 0; ks < 12; ks++) {
        const int s = ks >> 2, q = ks & 3;
        const int aoff = ((s == 1 ? 64 : 0) + q * 16) * 2;
        const int boff = ((s == 2 ? 64 : 0) + q * 16) * 2;
        uint32_t af[4][4], bf[2][4];
#pragma unroll
        for (int mi = 0; mi < 4; mi++) ldsm_x4(af[mi], aAddr[mi] + aoff);
#pragma unroll
        for (int nj = 0; nj < 2; nj++) ldsm_x4(bf[nj], bAddr[nj] + boff);
#pragma unroll
        for (int mi = 0; mi < 4; mi++)
#pragma unroll
            for (int nj = 0; nj < 2; nj++) {
                mma_bf16(acc[mi][nj * 2],     af[mi], &bf[nj][0]);
                mma_bf16(acc[mi][nj * 2 + 1], af[mi], &bf[nj][2]);
            }
    }

    // --- epilogue: split + transposed store into bf16 planes ---
#pragma unroll
    for (int mi = 0; mi < 4; mi++)
#pragma unroll
        for (int ni = 0; ni < 4; ni++) {
            const int m = mw + mi * 16 + (lane >> 2);
            const int n = col0 + nw + ni * 8 + (lane & 3) * 2;
#pragma unroll
            for (int r = 0; r < 4; r++) {
                const int mm = m + (r >> 1) * 8;
                const int nn = n + (r & 1);
                const size_t zrow = (size_t)(nn >> 2) * 256 + j * 4 + (nn & 3);
                __nv_bfloat16 h, l;
                split1(acc[mi][ni][r], h, l);
                g_Zhi[zrow * 8192 + row0 + mm] = h;
                g_Zlo[zrow * 8192 + row0 + mm] = l;
            }
        }
}

// ---------------------------------------------------------------------------
// Stage 2: tile M=128(b) x N=64(y), K=256 in 4 chunks of 64 (192 ext each).
// 8 warps (4m x 2n), warp tile 32b x 32y. Everything loaded via cp.async
// (A: Zhi/Zlo planes, rows [k][b]; B: w1e rows [y][hi|lo]), double-buffered.
// smem: A 2buf x 2seg x [64 k][272B]; B 2buf x [64 y][272B].
// ---------------------------------------------------------------------------
#define S2_STRIDE 272
#define S2_ASEG   17408              /* 64 * 272 */
#define S2_ABUF   (2 * S2_ASEG)      /* hi + lo */
#define S2_B_OFF  (2 * S2_ABUF)      /* 69632 */
#define S2_BBUF   17408
#define S2_SMEM   (S2_B_OFF + 2 * S2_BBUF) /* 104448 */

__global__ void __launch_bounds__(256, 2) s2_kernel() {
    extern __shared__ char sm[];
    const uint32_t sbA = smem_u32(sm), sbB = sbA + S2_B_OFF;

    const int tid = threadIdx.x, wid = tid >> 5, lane = tid & 31;
    const int ii   = blockIdx.x;
    const int row0 = blockIdx.y * 128;

    const int mw = (wid & 3) * 32;   // warp b tile (32 b)
    const int nw = (wid >> 2) * 32;  // warp y tile

    // loader mappings: r = row (k or y), c = 16B chunk
    const int lr = tid >> 2, lc = tid & 3;

    auto loadChunk = [&](int kc, int buf) {
        // A: both planes, rows k = ii*256 + kc*64 + lr, 128 b cols (256B)
        const size_t arow = (size_t)(ii * 256 + kc * 64 + lr) * 8192 + row0;
        const uint32_t adst = sbA + buf * S2_ABUF + lr * S2_STRIDE;
#pragma unroll
        for (int q = 0; q < 4; q++)
            cp16(adst + (lc + q * 4) * 16, reinterpret_cast<const char*>(g_Zhi + arow) + (lc + q * 4) * 16);
#pragma unroll
        for (int q = 0; q < 4; q++)
            cp16(adst + S2_ASEG + (lc + q * 4) * 16, reinterpret_cast<const char*>(g_Zlo + arow) + (lc + q * 4) * 16);
        // B: w1e rows y = lr, chunk block kc (256B)
        const char* bsrc = reinterpret_cast<const char*>(
            g_w1e + ((size_t)ii * 64 + lr) * 512 + kc * 128);
        const uint32_t bdst = sbB + buf * S2_BBUF + lr * S2_STRIDE;
#pragma unroll
        for (int q = 0; q < 4; q++)
            cp16(bdst + (lc + q * 4) * 16, bsrc + (lc + q * 4) * 16);
        CP_COMMIT();
    };

    float acc[2][4][4];
#pragma unroll
    for (int mi = 0; mi < 2; mi++)
#pragma unroll
        for (int n8 = 0; n8 < 4; n8++)
#pragma unroll
            for (int r = 0; r < 4; r++) acc[mi][n8][r] = 0.f;

    uint32_t aAddr[2], bAddr[2];
#pragma unroll
    for (int mi = 0; mi < 2; mi++)  // A is [k][b]: trans ldmatrix
        aAddr[mi] = sbA + (lane & 15) * S2_STRIDE + (mw + mi * 16 + (lane >> 4) * 8) * 2;
#pragma unroll
    for (int nj = 0; nj < 2; nj++)
        bAddr[nj] = sbB + (nw + nj * 16 + ((lane >> 4) << 3) + (lane & 7)) * S2_STRIDE
                        + (((lane >> 3) & 1) * 8) * 2;

    loadChunk(0, 0);

#pragma unroll 1
    for (int kc = 0; kc < 4; kc++) {
        const int buf = kc & 1;
        if (kc < 3) loadChunk(kc + 1, buf ^ 1);
        if (kc < 3) { CP_WAIT(1); } else { CP_WAIT(0); }
        __syncthreads();

        const uint32_t aBase = buf * S2_ABUF;
        const uint32_t bBase = buf * S2_BBUF;
        // s: A seg {hi,lo,hi}, B seg {hi,hi,lo}
#pragma unroll
        for (int s = 0; s < 3; s++) {
            const uint32_t aSeg = aBase + (s == 1 ? S2_ASEG : 0);
            const int boff = (s == 2 ? 64 : 0) * 2;
#pragma unroll
            for (int q = 0; q < 4; q++) {
                uint32_t t[2][4], bf[2][4];
#pragma unroll
                for (int mi = 0; mi < 2; mi++)
                    ldsm_x4_t(t[mi], aAddr[mi] + aSeg + q * 16 * S2_STRIDE);
#pragma unroll
                for (int nj = 0; nj < 2; nj++)
                    ldsm_x4(bf[nj], bAddr[nj] + bBase + boff + q * 32);
#pragma unroll
                for (int mi = 0; mi < 2; mi++) {
                    uint32_t af[4] = {t[mi][0], t[mi][2], t[mi][1], t[mi][3]};
#pragma unroll
                    for (int nj = 0; nj < 2; nj++) {
                        mma_bf16(acc[mi][nj * 2],     af, &bf[nj][0]);
                        mma_bf16(acc[mi][nj * 2 + 1], af, &bf[nj][2]);
                    }
                }
            }
        }
        __syncthreads();
    }

    // --- epilogue: coalesced store to g_O[(y*64+ii)][b] ---
#pragma unroll
    for (int mi = 0; mi < 2; mi++)
#pragma unroll
        for (int n8 = 0; n8 < 4; n8++)
#pragma unroll
            for (int r = 0; r < 4; r++) {
                const int m = mw + mi * 16 + (lane >> 2) + (r >> 1) * 8;
                const int y = nw + n8 * 8 + (lane & 3) * 2 + (r & 1);
                g_O[(size_t)(y * 64 + ii) * 8192 + row0 + m] = acc[mi][n8][r];
            }
}

// ---------------------------------------------------------------------------
// Final transpose: out[b][col] = g_O[col][b] + bias[col]. 32x32 smem tiles.
// ---------------------------------------------------------------------------
__global__ void __launch_bounds__(256) tr_kernel(const float* __restrict__ bias,
                                                 float* __restrict__ out) {
    __shared__ float t[32][33];
    const int b0 = blockIdx.x * 32, c0 = blockIdx.y * 32;
    const int tx = threadIdx.x & 31, ty = threadIdx.x >> 5;  // 32 x 8
#pragma unroll
    for (int i = 0; i < 4; i++)
        t[ty + i * 8][tx] = g_O[(size_t)(c0 + ty + i * 8) * 8192 + b0 + tx];
    __syncthreads();
#pragma unroll
    for (int i = 0; i < 4; i++)
        out[(size_t)(b0 + ty + i * 8) * 4096 + c0 + tx] = t[tx][ty + i * 8] + bias[c0 + tx];
}

extern "C" void kernel_launch(void* const* d_in, const int* in_sizes, int n_in,
                              void* d_out, int out_size) {
    const float* x    = (const float*)d_in[0];  // (8192, 4096)
    const float* c0   = (const float*)d_in[1];  // (64,64,64,4,1)
    const float* c1   = (const float*)d_in[2];  // (64,64,64,1,4)
    const float* bias = (const float*)d_in[3];  // (4096,)
    float* out = (float*)d_out;                 // (8192, 4096)

    cudaFuncSetAttribute(s1_kernel, cudaFuncAttributeMaxDynamicSharedMemorySize, S1_SMEM);
    cudaFuncSetAttribute(s2_kernel, cudaFuncAttributeMaxDynamicSharedMemorySize, S2_SMEM);

    prep0_kernel<<<64, 256>>>(c0);
    prep1_kernel<<<64, 256>>>(c1);
    s1_kernel<<<dim3(2, 64, 64), 256, S1_SMEM>>>(x);      // (ntile, mtile, j)
    s2_kernel<<<dim3(64, 64), 256, S2_SMEM>>>();          // (ii, mtile)
    tr_kernel<<<dim3(256, 128), 256>>>(bias, out);
}